// round 9
// baseline (speedup 1.0000x reference)
#include <cuda_runtime.h>

// Denoise_17669495455833: batched FISTA QP (2 passes x 100 iters, rows of 512 fp32).
// R8: latency-bound at 12 warps/SM (issue=66%, no pipe saturated).
//  - y moved to thread-private SMEM slots ([k][tid] layout, conflict-free LDS.64,
//    never shared across threads -> zero syncs). Saves 32 regs -> 4 CTAs/SM (16 warps).
//  - k-sweep reordered (2..15, then 1, then 0) so SHFL results (lat 26) are consumed
//    ~14 updates after issue instead of immediately.
//  - Same precombined pentadiagonal stencil as R7 (Jacobi semantics via rotating
//    old-z window + 3 saved old values for the tail updates).

typedef unsigned long long u64;
#define FULL_MASK 0xffffffffu

__device__ u64 g_coefs[100];   // packed (coef, coef) per iteration

__device__ __forceinline__ u64 pk2(float lo, float hi) {
    u64 r;
    asm("mov.b64 %0, {%1,%2};" : "=l"(r) : "r"(__float_as_uint(lo)), "r"(__float_as_uint(hi)));
    return r;
}
__device__ __forceinline__ void upk2(u64 v, float& lo, float& hi) {
    unsigned a, b;
    asm("mov.b64 {%0,%1}, %2;" : "=r"(a), "=r"(b) : "l"(v));
    lo = __uint_as_float(a); hi = __uint_as_float(b);
}
__device__ __forceinline__ u64 fma2(u64 a, u64 b, u64 c) {
    u64 d;
    asm("fma.rn.f32x2 %0, %1, %2, %3;" : "=l"(d) : "l"(a), "l"(b), "l"(c));
    return d;
}
__device__ __forceinline__ u64 add2(u64 a, u64 b) {
    u64 d;
    asm("add.rn.f32x2 %0, %1, %2;" : "=l"(d) : "l"(a), "l"(b));
    return d;
}
__device__ __forceinline__ u64 sub2(u64 a, u64 b) {
    u64 d;
    asm("sub.rn.f32x2 %0, %1, %2;" : "=l"(d) : "l"(a), "l"(b));
    return d;
}
__device__ __forceinline__ u64 mul2(u64 a, u64 b) {
    u64 d;
    asm("mul.rn.f32x2 %0, %1, %2;" : "=l"(d) : "l"(a), "l"(b));
    return d;
}
__device__ __forceinline__ u64 rep2(float f) {
    unsigned u = __float_as_uint(f);
    return ((u64)u << 32) | (u64)u;
}

__global__ void coef_setup_kernel() {
    if (threadIdx.x == 0 && blockIdx.x == 0) {
        float t = 1.0f;
        for (int i = 0; i < 100; ++i) {
            float tn = 0.5f * (1.0f + sqrtf(fmaf(4.0f * t, t, 1.0f)));
            float c  = (t - 1.0f) / tn;
            unsigned u = __float_as_uint(c);
            g_coefs[i] = ((u64)u << 32) | (u64)u;
            t = tn;
        }
    }
}

// LAM = 10, step = 1/322.  v = z + CZY*(z-y) + CDT*DtD(z), CZY=-2/322, CDT=-20/322.
#define STEPf (1.0f / 322.0f)
#define CZYf  (-2.0f * STEPf)
#define CDTf  (-2.0f * 10.0f * STEPf)

__global__ void __launch_bounds__(128, 4)
denoise_fista6_kernel(const float* __restrict__ in, float* __restrict__ out, int nrows)
{
    __shared__ u64 ysm[16][128];   // thread-private y slots: ysm[k][tid], stride 8B -> no conflicts

    const int tid  = (int)threadIdx.x;
    const int gw   = (int)((blockIdx.x * blockDim.x + threadIdx.x) >> 5);  // warp = row pair
    const int lane = tid & 31;
    if (gw * 2 + 1 >= nrows) return;

    const float* rA = in + (size_t)(gw * 2)     * 512 + lane * 16;
    const float* rB = in + (size_t)(gw * 2 + 1) * 512 + lane * 16;

    u64 x[16], z[16];
    #pragma unroll
    for (int i = 0; i < 16; i += 4) {
        float4 a4 = *reinterpret_cast<const float4*>(rA + i);
        float4 b4 = *reinterpret_cast<const float4*>(rB + i);
        u64 p0 = pk2(a4.x, b4.x), p1_ = pk2(a4.y, b4.y);
        u64 p2_ = pk2(a4.z, b4.z), p3 = pk2(a4.w, b4.w);
        ysm[i + 0][tid] = p0; ysm[i + 1][tid] = p1_;
        ysm[i + 2][tid] = p2_; ysm[i + 3][tid] = p3;
        x[i + 0] = p0;  x[i + 1] = p1_;  x[i + 2] = p2_;  x[i + 3] = p3;
        z[i + 0] = p0;  z[i + 1] = p1_;  z[i + 2] = p2_;  z[i + 3] = p3;
    }

    const u64 CA = rep2(1.0f + CZYf + 6.0f * CDTf);   // z_j
    const u64 CB = rep2(-4.0f * CDTf);                // z_{j+-1}
    const u64 CC = rep2(CDTf);                        // z_{j+-2}
    const u64 CE = rep2(-CZYf);                       // y_j
    // boundary corrections (true DtD row minus zero-padded interior stencil), x CDT:
    const u64 Q1 = rep2(-5.0f * CDTf);
    const u64 Q2 = rep2( 2.0f * CDTf);
    const u64 Q3 = rep2(-1.0f * CDTf);

    const bool first = (lane == 0);
    const bool last  = (lane == 31);

    #pragma unroll 1
    for (int pass = 0; pass < 2; ++pass) {

        #pragma unroll 1
        for (int it = 0; it < 100; ++it) {
            const u64 coefP = g_coefs[it];

            // neighbor pairs (previous iterate); out-of-range -> 0
            u64 zm2 = __shfl_up_sync  (FULL_MASK, z[14], 1);
            u64 zm1 = __shfl_up_sync  (FULL_MASK, z[15], 1);
            u64 zp1 = __shfl_down_sync(FULL_MASK, z[0],  1);
            u64 zp2 = __shfl_down_sync(FULL_MASK, z[1],  1);
            if (first) { zm2 = 0ULL; zm1 = 0ULL; }
            if (last)  { zp1 = 0ULL; zp2 = 0ULL; }

            // saved old values needed by the deferred k=1, k=0 updates
            const u64 oz1 = z[1], oz2 = z[2], oz3 = z[3];

            // ---- main sweep k = 2..15 (shuffle results consumed only at k=14,15) ----
            u64 p2 = z[0], p1 = z[1];   // rotating window of OLD z[k-2], z[k-1]
            #pragma unroll
            for (int k = 2; k < 16; ++k) {
                u64 zc  = z[k];
                u64 zR1 = (k <= 14) ? z[k + 1] : zp1;
                u64 zR2 = (k <= 13) ? z[k + 2] : ((k == 14) ? zp1 : zp2);
                u64 yk  = ysm[k][tid];

                u64 s1 = add2(p1, zR1);
                u64 s2 = add2(p2, zR2);
                u64 v  = mul2(yk, CE);
                v = fma2(zc, CA, v);
                v = fma2(s1, CB, v);
                v = fma2(s2, CC, v);
                if (k == 14 && last) { v = fma2(zc, Q3, v); v = fma2(z[15], Q2, v); }
                if (k == 15 && last) { v = fma2(p1, Q2, v); v = fma2(zc,    Q1, v); }

                float vlo, vhi, ylo, yhi;
                upk2(v, vlo, vhi);
                upk2(yk, ylo, yhi);
                float xlo = fminf(fmaxf(vlo, 0.0f), ylo);
                float xhi = fminf(fmaxf(vhi, 0.0f), yhi);
                u64 xn = pk2(xlo, xhi);

                u64 dx = sub2(xn, x[k]);
                z[k] = fma2(dx, coefP, xn);
                x[k] = xn;

                p2 = p1; p1 = zc;
            }

            // ---- k = 1 (old z[0] still intact; right neighbors from saved oz2, oz3) ----
            {
                u64 zc = oz1;
                u64 yk = ysm[1][tid];
                u64 s1 = add2(z[0], oz2);
                u64 s2 = add2(zm1,  oz3);
                u64 v  = mul2(yk, CE);
                v = fma2(zc, CA, v);
                v = fma2(s1, CB, v);
                v = fma2(s2, CC, v);
                if (first) { v = fma2(z[0], Q2, v); v = fma2(zc, Q3, v); }

                float vlo, vhi, ylo, yhi;
                upk2(v, vlo, vhi);
                upk2(yk, ylo, yhi);
                u64 xn = pk2(fminf(fmaxf(vlo, 0.0f), ylo),
                             fminf(fmaxf(vhi, 0.0f), yhi));
                u64 dx = sub2(xn, x[1]);
                z[1] = fma2(dx, coefP, xn);
                x[1] = xn;
            }

            // ---- k = 0 (right neighbors from saved oz1, oz2) ----
            {
                u64 zc = z[0];
                u64 yk = ysm[0][tid];
                u64 s1 = add2(zm1, oz1);
                u64 s2 = add2(zm2, oz2);
                u64 v  = mul2(yk, CE);
                v = fma2(zc, CA, v);
                v = fma2(s1, CB, v);
                v = fma2(s2, CC, v);
                if (first) { v = fma2(zc, Q1, v); v = fma2(oz1, Q2, v); }

                float vlo, vhi, ylo, yhi;
                upk2(v, vlo, vhi);
                upk2(yk, ylo, yhi);
                u64 xn = pk2(fminf(fmaxf(vlo, 0.0f), ylo),
                             fminf(fmaxf(vhi, 0.0f), yhi));
                u64 dx = sub2(xn, x[0]);
                z[0] = fma2(dx, coefP, xn);
                x[0] = xn;
            }
        }

        if (pass == 0) {
            // pass 2 solves with y = pass-1 output; reset z to x0 = proj(y) = y = x
            #pragma unroll
            for (int k = 0; k < 16; ++k) { ysm[k][tid] = x[k]; z[k] = x[k]; }
        }
    }

    float* oA = out + (size_t)(gw * 2)     * 512 + lane * 16;
    float* oB = out + (size_t)(gw * 2 + 1) * 512 + lane * 16;
    #pragma unroll
    for (int i = 0; i < 16; i += 4) {
        float4 a4, b4;
        upk2(x[i + 0], a4.x, b4.x);
        upk2(x[i + 1], a4.y, b4.y);
        upk2(x[i + 2], a4.z, b4.z);
        upk2(x[i + 3], a4.w, b4.w);
        *reinterpret_cast<float4*>(oA + i) = a4;
        *reinterpret_cast<float4*>(oB + i) = b4;
    }
}

extern "C" void kernel_launch(void* const* d_in, const int* in_sizes, int n_in,
                              void* d_out, int out_size)
{
    const float* in  = (const float*)d_in[0];
    float*       out = (float*)d_out;
    const int nrows  = in_sizes[0] / 512;            // 16384 rows
    coef_setup_kernel<<<1, 32>>>();
    const int warps  = nrows / 2;                    // 2 rows per warp
    const int blocks = (warps + 3) / 4;              // 4 warps per block
    denoise_fista6_kernel<<<blocks, 128>>>(in, out, nrows);
}

// round 10
// speedup vs baseline: 1.0490x; 1.0490x over previous
#include <cuda_runtime.h>

// Denoise_17669495455833: batched FISTA QP (2 passes x 100 iters, rows of 512 fp32).
// R9: exact R7 body (best: 589us, 144 regs) with 64-thread CTAs.
// At 144 regs, block=128 fits 3 CTAs/SM = 12 warps (wastes 10K regs);
// block=64 fits 7 CTAs/SM = 14 warps. Latency-bound (issue 66%) -> more warps.
// R5/R8 lesson: never trade registers for per-iteration memory traffic.

typedef unsigned long long u64;
#define FULL_MASK 0xffffffffu

__device__ u64 g_coefs[100];   // packed (coef, coef) per iteration

__device__ __forceinline__ u64 pk2(float lo, float hi) {
    u64 r;
    asm("mov.b64 %0, {%1,%2};" : "=l"(r) : "r"(__float_as_uint(lo)), "r"(__float_as_uint(hi)));
    return r;
}
__device__ __forceinline__ void upk2(u64 v, float& lo, float& hi) {
    unsigned a, b;
    asm("mov.b64 {%0,%1}, %2;" : "=r"(a), "=r"(b) : "l"(v));
    lo = __uint_as_float(a); hi = __uint_as_float(b);
}
__device__ __forceinline__ u64 fma2(u64 a, u64 b, u64 c) {
    u64 d;
    asm("fma.rn.f32x2 %0, %1, %2, %3;" : "=l"(d) : "l"(a), "l"(b), "l"(c));
    return d;
}
__device__ __forceinline__ u64 add2(u64 a, u64 b) {
    u64 d;
    asm("add.rn.f32x2 %0, %1, %2;" : "=l"(d) : "l"(a), "l"(b));
    return d;
}
__device__ __forceinline__ u64 sub2(u64 a, u64 b) {
    u64 d;
    asm("sub.rn.f32x2 %0, %1, %2;" : "=l"(d) : "l"(a), "l"(b));
    return d;
}
__device__ __forceinline__ u64 mul2(u64 a, u64 b) {
    u64 d;
    asm("mul.rn.f32x2 %0, %1, %2;" : "=l"(d) : "l"(a), "l"(b));
    return d;
}
__device__ __forceinline__ u64 rep2(float f) {
    unsigned u = __float_as_uint(f);
    return ((u64)u << 32) | (u64)u;
}

__global__ void coef_setup_kernel() {
    if (threadIdx.x == 0 && blockIdx.x == 0) {
        float t = 1.0f;
        for (int i = 0; i < 100; ++i) {
            float tn = 0.5f * (1.0f + sqrtf(fmaf(4.0f * t, t, 1.0f)));
            float c  = (t - 1.0f) / tn;
            unsigned u = __float_as_uint(c);
            g_coefs[i] = ((u64)u << 32) | (u64)u;
            t = tn;
        }
    }
}

__global__ void __launch_bounds__(64)
denoise_fista7_kernel(const float* __restrict__ in, float* __restrict__ out, int nrows)
{
    const int gw   = (int)((blockIdx.x * blockDim.x + threadIdx.x) >> 5);  // warp = row pair
    const int lane = (int)(threadIdx.x & 31);
    if (gw * 2 + 1 >= nrows) return;

    const float* rA = in + (size_t)(gw * 2)     * 512 + lane * 16;
    const float* rB = in + (size_t)(gw * 2 + 1) * 512 + lane * 16;

    u64 y[16], x[16], z[16];
    #pragma unroll
    for (int i = 0; i < 16; i += 4) {
        float4 a4 = *reinterpret_cast<const float4*>(rA + i);
        float4 b4 = *reinterpret_cast<const float4*>(rB + i);
        y[i + 0] = pk2(a4.x, b4.x);
        y[i + 1] = pk2(a4.y, b4.y);
        y[i + 2] = pk2(a4.z, b4.z);
        y[i + 3] = pk2(a4.w, b4.w);
    }

    // LAM = 10, step = 1/322.
    // v = z + CZY*(z-y) + CDT*DtD(z),  CZY = -2/322, CDT = -20/322. Precombined:
    const float STEPf = 1.0f / 322.0f;
    const float CZYf  = -2.0f * STEPf;
    const float CDTf  = -2.0f * 10.0f * STEPf;
    const u64 CA = rep2(1.0f + CZYf + 6.0f * CDTf);   // z_j
    const u64 CB = rep2(-4.0f * CDTf);                // z_{j+-1}
    const u64 CC = rep2(CDTf);                        // z_{j+-2}
    const u64 CE = rep2(-CZYf);                       // y_j
    // boundary corrections (true DtD row minus zero-padded interior stencil), x CDT:
    const u64 Q1 = rep2(-5.0f * CDTf);
    const u64 Q2 = rep2( 2.0f * CDTf);
    const u64 Q3 = rep2(-1.0f * CDTf);

    const bool first = (lane == 0);
    const bool last  = (lane == 31);

    #pragma unroll 1
    for (int pass = 0; pass < 2; ++pass) {
        #pragma unroll
        for (int k = 0; k < 16; ++k) { x[k] = y[k]; z[k] = y[k]; }   // x0 = proj(y) = y

        #pragma unroll 1
        for (int it = 0; it < 100; ++it) {
            // neighbor pairs (previous iterate); out-of-range -> 0
            u64 zm2 = __shfl_up_sync  (FULL_MASK, z[14], 1);
            u64 zm1 = __shfl_up_sync  (FULL_MASK, z[15], 1);
            u64 zp1 = __shfl_down_sync(FULL_MASK, z[0],  1);
            u64 zp2 = __shfl_down_sync(FULL_MASK, z[1],  1);
            if (first) { zm2 = 0ULL; zm1 = 0ULL; }
            if (last)  { zp1 = 0ULL; zp2 = 0ULL; }

            const u64 coefP = g_coefs[it];

            // rotating window of OLD z values (z[] is overwritten in place)
            u64 p2 = zm2, p1 = zm1;

            #pragma unroll
            for (int k = 0; k < 16; ++k) {
                u64 zc  = z[k];                                 // old z_j
                u64 zR1 = (k <= 14) ? z[k + 1] : zp1;           // old z_{j+1}
                u64 zR2 = (k <= 13) ? z[k + 2] : ((k == 14) ? zp1 : zp2);  // old z_{j+2}

                u64 s1 = add2(p1, zR1);             // rt2
                u64 s2 = add2(p2, zR2);             // rt2
                u64 v  = mul2(y[k], CE);            // rt2
                v = fma2(zc, CA, v);                // rt3
                v = fma2(s1, CB, v);                // rt3
                v = fma2(s2, CC, v);                // rt3

                // true DtD boundary rows (old values: p1 = old left neighbor)
                if (k == 0) {
                    if (first) { v = fma2(zc, Q1, v); v = fma2(z[1], Q2, v); }
                }
                if (k == 1) {
                    if (first) { v = fma2(p1, Q2, v); v = fma2(zc, Q3, v); }
                }
                if (k == 14) {
                    if (last)  { v = fma2(zc, Q3, v); v = fma2(z[15], Q2, v); }
                }
                if (k == 15) {
                    if (last)  { v = fma2(p1, Q2, v); v = fma2(zc, Q1, v); }
                }

                // x_new = clip(v, 0, y)  (scalar FMNMX -> alu pipe)
                float vlo, vhi, ylo, yhi;
                upk2(v, vlo, vhi);
                upk2(y[k], ylo, yhi);
                float xlo = fminf(fmaxf(vlo, 0.0f), ylo);
                float xhi = fminf(fmaxf(vhi, 0.0f), yhi);
                u64 xn = pk2(xlo, xhi);

                // z_new = x_new + coef*(x_new - x)
                u64 dx = sub2(xn, x[k]);            // rt2
                z[k] = fma2(dx, coefP, xn);         // rt3
                x[k] = xn;

                p2 = p1; p1 = zc;
            }
        }

        if (pass == 0) {
            #pragma unroll
            for (int k = 0; k < 16; ++k) y[k] = x[k];   // pass 2: y = pass-1 output
        }
    }

    float* oA = out + (size_t)(gw * 2)     * 512 + lane * 16;
    float* oB = out + (size_t)(gw * 2 + 1) * 512 + lane * 16;
    #pragma unroll
    for (int i = 0; i < 16; i += 4) {
        float4 a4, b4;
        upk2(x[i + 0], a4.x, b4.x);
        upk2(x[i + 1], a4.y, b4.y);
        upk2(x[i + 2], a4.z, b4.z);
        upk2(x[i + 3], a4.w, b4.w);
        *reinterpret_cast<float4*>(oA + i) = a4;
        *reinterpret_cast<float4*>(oB + i) = b4;
    }
}

extern "C" void kernel_launch(void* const* d_in, const int* in_sizes, int n_in,
                              void* d_out, int out_size)
{
    const float* in  = (const float*)d_in[0];
    float*       out = (float*)d_out;
    const int nrows  = in_sizes[0] / 512;            // 16384 rows
    coef_setup_kernel<<<1, 32>>>();
    const int warps  = nrows / 2;                    // 2 rows per warp
    const int blocks = (warps + 1) / 2;              // 2 warps per 64-thread block
    denoise_fista7_kernel<<<blocks, 64>>>(in, out, nrows);
}